// round 3
// baseline (speedup 1.0000x reference)
#include <cuda_runtime.h>

#define B_   256
#define N_   196
#define C_   768
#define H_   12
#define HD_  64
#define C3_  2304

// Scratch (device globals: allocation-free per harness rules)
__device__ float g_qkv[(size_t)B_ * N_ * C3_];   // [B,N,3C]
__device__ float g_att[(size_t)B_ * N_ * C_];    // [B,N,C] attention output
__device__ float g_rpb[(size_t)H_ * N_ * N_];    // [H,N,N] pre-gathered bias
__device__ float g_bias[C3_];                    // fused qkv bias

// ---------------------------------------------------------------------------
// Small init kernels
// ---------------------------------------------------------------------------
__global__ void bias_init_kernel(const float* __restrict__ qb,
                                 const float* __restrict__ vb) {
    int i = blockIdx.x * blockDim.x + threadIdx.x;
    if (i < C3_) {
        float v = 0.0f;
        if (i < C_)            v = qb[i];
        else if (i >= 2 * C_)  v = vb[i - 2 * C_];
        g_bias[i] = v;
    }
}

__global__ void rpb_init_kernel(const float* __restrict__ table,
                                const int* __restrict__ rel) {
    int i = blockIdx.x * blockDim.x + threadIdx.x;
    if (i < H_ * N_ * N_) {
        int h  = i / (N_ * N_);
        int ij = i - h * (N_ * N_);
        g_rpb[i] = table[rel[ij] * H_ + h];
    }
}

// ---------------------------------------------------------------------------
// SGEMM: C[M,N] = A[M,K] @ W[N,K]^T + bias[N]
// 128x128 block tile, BK=16, 256 threads, 8x8 micro-tile,
// register-prefetch pipelining on global loads, float4 everywhere.
// Requires M%128==0, N%128==0, K%16==0 (true for all our shapes).
// ---------------------------------------------------------------------------
__global__ void __launch_bounds__(256)
sgemm_bias_kernel(const float* __restrict__ A, const float* __restrict__ W,
                  const float* __restrict__ bias, float* __restrict__ Cmat,
                  int M, int N, int K) {
    __shared__ float As[16][128];   // [k][m]
    __shared__ float Bs[16][128];   // [k][n]

    const int tid = threadIdx.x;
    const int tx  = tid & 15;           // n dir
    const int ty  = tid >> 4;           // m dir
    const int m0  = blockIdx.y << 7;
    const int n0  = blockIdx.x << 7;

    // Global-load assignment: 512 float4 per tile per matrix, 2 per thread.
    // idx in [0,512): row = idx>>2 (0..127), kchunk = (idx&3)*4
    const int r0 = tid >> 2;            // rows tid>>2 and (tid+256)>>2
    const int r1 = (tid + 256) >> 2;
    const int kc0 = (tid & 3) << 2;
    const int kc1 = ((tid + 256) & 3) << 2;  // == kc0, but keep general

    const float* Ap0 = A + (size_t)(m0 + r0) * K + kc0;
    const float* Ap1 = A + (size_t)(m0 + r1) * K + kc1;
    const float* Wp0 = W + (size_t)(n0 + r0) * K + kc0;
    const float* Wp1 = W + (size_t)(n0 + r1) * K + kc1;

    float acc[8][8];
#pragma unroll
    for (int i = 0; i < 8; i++)
#pragma unroll
        for (int j = 0; j < 8; j++) acc[i][j] = 0.0f;

    // Preload tile 0 into registers
    float4 a0 = *(const float4*)(Ap0);
    float4 a1 = *(const float4*)(Ap1);
    float4 b0 = *(const float4*)(Wp0);
    float4 b1 = *(const float4*)(Wp1);

    const int nTiles = K >> 4;
    for (int t = 0; t < nTiles; t++) {
        // Store staged registers to smem (transposed: [k][row])
        As[kc0 + 0][r0] = a0.x; As[kc0 + 1][r0] = a0.y;
        As[kc0 + 2][r0] = a0.z; As[kc0 + 3][r0] = a0.w;
        As[kc1 + 0][r1] = a1.x; As[kc1 + 1][r1] = a1.y;
        As[kc1 + 2][r1] = a1.z; As[kc1 + 3][r1] = a1.w;
        Bs[kc0 + 0][r0] = b0.x; Bs[kc0 + 1][r0] = b0.y;
        Bs[kc0 + 2][r0] = b0.z; Bs[kc0 + 3][r0] = b0.w;
        Bs[kc1 + 0][r1] = b1.x; Bs[kc1 + 1][r1] = b1.y;
        Bs[kc1 + 2][r1] = b1.z; Bs[kc1 + 3][r1] = b1.w;
        __syncthreads();

        // Prefetch next tile from global while computing this one
        if (t + 1 < nTiles) {
            int ko = (t + 1) << 4;
            a0 = *(const float4*)(Ap0 + ko);
            a1 = *(const float4*)(Ap1 + ko);
            b0 = *(const float4*)(Wp0 + ko);
            b1 = *(const float4*)(Wp1 + ko);
        }

#pragma unroll
        for (int k = 0; k < 16; k++) {
            float4 avL = *(const float4*)&As[k][ty << 2];
            float4 avH = *(const float4*)&As[k][(ty << 2) + 64];
            float4 bvL = *(const float4*)&Bs[k][tx << 2];
            float4 bvH = *(const float4*)&Bs[k][(tx << 2) + 64];
            float am[8] = {avL.x, avL.y, avL.z, avL.w,
                           avH.x, avH.y, avH.z, avH.w};
            float bm[8] = {bvL.x, bvL.y, bvL.z, bvL.w,
                           bvH.x, bvH.y, bvH.z, bvH.w};
#pragma unroll
            for (int i = 0; i < 8; i++)
#pragma unroll
                for (int j = 0; j < 8; j++)
                    acc[i][j] += am[i] * bm[j];
        }
        __syncthreads();
    }

    // Epilogue with bias. Column groups: n0+tx*4 (j 0..3), n0+64+tx*4 (j 4..7)
    const int nbL = n0 + (tx << 2);
    const int nbH = nbL + 64;
    float4 biasL = *(const float4*)(bias + nbL);
    float4 biasH = *(const float4*)(bias + nbH);
    float bbL[4] = {biasL.x, biasL.y, biasL.z, biasL.w};
    float bbH[4] = {biasH.x, biasH.y, biasH.z, biasH.w};

#pragma unroll
    for (int i = 0; i < 8; i++) {
        int m = m0 + (ty << 2) + (i & 3) + ((i >> 2) << 6);  // +64 for i>=4
        float* crow = Cmat + (size_t)m * N;
        float4 oL, oH;
        oL.x = acc[i][0] + bbL[0]; oL.y = acc[i][1] + bbL[1];
        oL.z = acc[i][2] + bbL[2]; oL.w = acc[i][3] + bbL[3];
        oH.x = acc[i][4] + bbH[0]; oH.y = acc[i][5] + bbH[1];
        oH.z = acc[i][6] + bbH[2]; oH.w = acc[i][7] + bbH[3];
        *(float4*)(crow + nbL) = oL;
        *(float4*)(crow + nbH) = oH;
    }
}

// ---------------------------------------------------------------------------
// Fused attention: one CTA per (b,h). Q(scaled)/K^T/V tiles in smem,
// 1 row per warp, warp softmax, AV with smem-broadcast p.
// ---------------------------------------------------------------------------
#define KT_LD 200
#define ATTN_SMEM_FLOATS (N_*HD_ + HD_*KT_LD + N_*HD_ + 8*N_)

__global__ void __launch_bounds__(256)
attn_kernel(const float* __restrict__ qkv, float* __restrict__ out) {
    extern __shared__ float sm[];
    float* sq  = sm;                      // [196][64]  q * scale
    float* skT = sq  + N_ * HD_;          // [64][200]  k transposed
    float* sv  = skT + HD_ * KT_LD;       // [196][64]  v
    float* sp  = sv  + N_ * HD_;          // [8][196]   per-warp p row

    const int tid = threadIdx.x;
    const int b   = blockIdx.x / H_;
    const int h   = blockIdx.x - b * H_;
    const float scale = 0.125f;           // 64^-0.5

    const float* base = qkv + (size_t)b * N_ * C3_ + h * HD_;
    for (int idx = tid; idx < N_ * HD_; idx += 256) {
        int n = idx >> 6, d = idx & 63;
        const float* src = base + (size_t)n * C3_ + d;
        sq[idx]            = src[0] * scale;
        skT[d * KT_LD + n] = src[C_];
        sv[idx]            = src[2 * C_];
    }
    __syncthreads();

    const int wid  = tid >> 5;
    const int lane = tid & 31;
    const float* rpbh = g_rpb + (size_t)h * (N_ * N_);

    for (int i = wid; i < N_; i += 8) {
        float s[7];
#pragma unroll
        for (int t = 0; t < 7; t++) s[t] = 0.0f;

        const float* qrow = sq + i * HD_;
        const float* kcol = skT + lane;
#pragma unroll 4
        for (int d = 0; d < HD_; d++) {
            float qd = qrow[d];
            const float* kr = kcol + d * KT_LD;
#pragma unroll
            for (int t = 0; t < 6; t++) s[t] += qd * kr[t * 32];
            if (lane < 4) s[6] += qd * kr[192];
        }

        const float* rrow = rpbh + i * N_;
#pragma unroll
        for (int t = 0; t < 6; t++) s[t] += rrow[lane + t * 32];
        if (lane < 4) s[6] += rrow[lane + 192];
        else          s[6] = -3.4e38f;

        float mx = s[0];
#pragma unroll
        for (int t = 1; t < 7; t++) mx = fmaxf(mx, s[t]);
#pragma unroll
        for (int o = 16; o > 0; o >>= 1)
            mx = fmaxf(mx, __shfl_xor_sync(0xffffffffu, mx, o));

        float sum = 0.0f;
#pragma unroll
        for (int t = 0; t < 7; t++) {
            float e = (t < 6 || lane < 4) ? __expf(s[t] - mx) : 0.0f;
            s[t] = e;
            sum += e;
        }
#pragma unroll
        for (int o = 16; o > 0; o >>= 1)
            sum += __shfl_xor_sync(0xffffffffu, sum, o);
        float inv = 1.0f / sum;

        float* prow = sp + wid * N_;
#pragma unroll
        for (int t = 0; t < 6; t++) prow[lane + t * 32] = s[t] * inv;
        if (lane < 4) prow[lane + 192] = s[6] * inv;
        __syncwarp();

        float a0 = 0.f, a1 = 0.f, a2 = 0.f, a3 = 0.f;
        for (int j = 0; j < N_; j += 2) {
            float p0 = prow[j];
            float p1 = prow[j + 1];
            const float* v0 = sv + j * HD_ + lane;
            a0 += p0 * v0[0];
            a1 += p0 * v0[32];
            a2 += p1 * v0[HD_];
            a3 += p1 * v0[HD_ + 32];
        }
        a0 += a2;
        a1 += a3;

        float* orow = out + ((size_t)b * N_ + i) * C_ + h * HD_;
        orow[lane]      = a0;
        orow[lane + 32] = a1;
        __syncwarp();   // protect sp reuse next iteration
    }
}

// ---------------------------------------------------------------------------
// Launch
// ---------------------------------------------------------------------------
extern "C" void kernel_launch(void* const* d_in, const int* in_sizes, int n_in,
                              void* d_out, int out_size) {
    const float* x         = (const float*)d_in[0];
    const float* qkv_w     = (const float*)d_in[1];
    const float* q_bias    = (const float*)d_in[2];
    const float* v_bias    = (const float*)d_in[3];
    const float* rpb_table = (const float*)d_in[4];
    const float* proj_w    = (const float*)d_in[5];
    const float* proj_b    = (const float*)d_in[6];
    const int*   rel_index = (const int*)d_in[7];
    float*       out       = (float*)d_out;

    // Host-side, non-stream calls: legal during graph capture, idempotent.
    static const size_t attn_smem = ATTN_SMEM_FLOATS * sizeof(float);
    cudaFuncSetAttribute(attn_kernel,
                         cudaFuncAttributeMaxDynamicSharedMemorySize,
                         (int)attn_smem);

    float *qkvbuf, *attbuf, *biasbuf;
    cudaGetSymbolAddress((void**)&qkvbuf, g_qkv);
    cudaGetSymbolAddress((void**)&attbuf, g_att);
    cudaGetSymbolAddress((void**)&biasbuf, g_bias);

    // 1. fused qkv bias
    bias_init_kernel<<<(C3_ + 255) / 256, 256>>>(q_bias, v_bias);

    // 2. pre-gather relative position bias [H,N,N]
    rpb_init_kernel<<<(H_ * N_ * N_ + 255) / 256, 256>>>(rpb_table, rel_index);

    // 3. QKV GEMM: [B*N, C] x [3C, C]^T -> [B*N, 3C]
    {
        dim3 grid(C3_ / 128, (B_ * N_) / 128);
        sgemm_bias_kernel<<<grid, 256>>>(x, qkv_w, biasbuf, qkvbuf,
                                         B_ * N_, C3_, C_);
    }

    // 4. fused attention per (b,h)
    attn_kernel<<<B_ * H_, 256, attn_smem>>>(qkvbuf, attbuf);

    // 5. Proj GEMM: [B*N, C] x [C, C]^T -> d_out
    {
        dim3 grid(C_ / 128, (B_ * N_) / 128);
        sgemm_bias_kernel<<<grid, 256>>>(attbuf, proj_w, proj_b, out,
                                         B_ * N_, C_, C_);
    }
}

// round 4
// speedup vs baseline: 1.9675x; 1.9675x over previous
#include <cuda_runtime.h>
#include <cstdint>

#define B_   256
#define N_   196
#define C_   768
#define H_   12
#define HD_  64
#define C3_  2304

// Scratch (device globals: allocation-free per harness rules)
__device__ float g_qkv[(size_t)B_ * N_ * C3_];   // [B,N,3C]
__device__ float g_att[(size_t)B_ * N_ * C_];    // [B,N,C] attention output
__device__ float g_rpb[(size_t)H_ * N_ * N_];    // [H,N,N] pre-gathered bias
__device__ float g_bias[C3_];                    // fused qkv bias

// ---------------------------------------------------------------------------
// Small init kernels
// ---------------------------------------------------------------------------
__global__ void bias_init_kernel(const float* __restrict__ qb,
                                 const float* __restrict__ vb) {
    int i = blockIdx.x * blockDim.x + threadIdx.x;
    if (i < C3_) {
        float v = 0.0f;
        if (i < C_)            v = qb[i];
        else if (i >= 2 * C_)  v = vb[i - 2 * C_];
        g_bias[i] = v;
    }
}

__global__ void rpb_init_kernel(const float* __restrict__ table,
                                const int* __restrict__ rel) {
    int i = blockIdx.x * blockDim.x + threadIdx.x;
    if (i < H_ * N_ * N_) {
        int h  = i / (N_ * N_);
        int ij = i - h * (N_ * N_);
        g_rpb[i] = table[rel[ij] * H_ + h];
    }
}

// ---------------------------------------------------------------------------
// tf32 helpers
// ---------------------------------------------------------------------------
__device__ __forceinline__ uint32_t f2tf32(float f) {
    uint32_t r;
    asm("cvt.rna.tf32.f32 %0, %1;" : "=r"(r) : "f"(f));
    return r;
}

__device__ __forceinline__ void mma_tf32(float* c, const uint32_t* a,
                                         uint32_t b0, uint32_t b1) {
    asm volatile(
        "mma.sync.aligned.m16n8k8.row.col.f32.tf32.tf32.f32 "
        "{%0,%1,%2,%3}, {%4,%5,%6,%7}, {%8,%9}, {%0,%1,%2,%3};"
        : "+f"(c[0]), "+f"(c[1]), "+f"(c[2]), "+f"(c[3])
        : "r"(a[0]), "r"(a[1]), "r"(a[2]), "r"(a[3]), "r"(b0), "r"(b1));
}

// ---------------------------------------------------------------------------
// Tensor-core GEMM: C[M,N] = A[M,K] @ W[N,K]^T + bias[N]   (tf32 MMA)
// 128x128 CTA tile, BK=32, 256 threads (8 warps, 4m x 2n), warp tile m32n64.
// Requires M%128==0, N%128==0, K%32==0.
// ---------------------------------------------------------------------------
#define TG_LDS 36   // padded smem row stride (elements)

__global__ void __launch_bounds__(256)
tgemm_bias_kernel(const float* __restrict__ A, const float* __restrict__ W,
                  const float* __restrict__ bias, float* __restrict__ Cmat,
                  int M, int N, int K) {
    __shared__ uint32_t As[128 * TG_LDS];
    __shared__ uint32_t Bs[128 * TG_LDS];

    const int tid  = threadIdx.x;
    const int lane = tid & 31;
    const int wid  = tid >> 5;
    const int gid  = lane >> 2;   // 0..7
    const int tig  = lane & 3;    // 0..3
    const int wm   = wid & 3;     // warp m index (0..3) -> 32 rows
    const int wn   = wid >> 2;    // warp n index (0..1) -> 64 cols
    const int m0   = blockIdx.y << 7;
    const int n0   = blockIdx.x << 7;

    // Global staging: 4 float4 per matrix per thread (128x32 tile)
    const int row_ = tid >> 3;          // + i*32
    const int kq   = (tid & 7) << 2;

    const float* Ap = A + (size_t)(m0 + row_) * K + kq;
    const float* Wp = W + (size_t)(n0 + row_) * K + kq;

    float acc[2][8][4];
#pragma unroll
    for (int mi = 0; mi < 2; mi++)
#pragma unroll
        for (int ni = 0; ni < 8; ni++)
#pragma unroll
            for (int j = 0; j < 4; j++) acc[mi][ni][j] = 0.0f;

    float4 ap[4], bp[4];
#pragma unroll
    for (int i = 0; i < 4; i++) {
        ap[i] = *(const float4*)(Ap + (size_t)(i * 32) * K);
        bp[i] = *(const float4*)(Wp + (size_t)(i * 32) * K);
    }

    const int nT = K >> 5;
    for (int t = 0; t < nT; t++) {
        // Stage (convert fp32 -> tf32 with RNA rounding)
#pragma unroll
        for (int i = 0; i < 4; i++) {
            uint32_t* da = &As[(row_ + i * 32) * TG_LDS + kq];
            da[0] = f2tf32(ap[i].x); da[1] = f2tf32(ap[i].y);
            da[2] = f2tf32(ap[i].z); da[3] = f2tf32(ap[i].w);
            uint32_t* db = &Bs[(row_ + i * 32) * TG_LDS + kq];
            db[0] = f2tf32(bp[i].x); db[1] = f2tf32(bp[i].y);
            db[2] = f2tf32(bp[i].z); db[3] = f2tf32(bp[i].w);
        }
        __syncthreads();

        // Prefetch next tile while computing
        if (t + 1 < nT) {
            int ko = (t + 1) << 5;
#pragma unroll
            for (int i = 0; i < 4; i++) {
                ap[i] = *(const float4*)(Ap + (size_t)(i * 32) * K + ko);
                bp[i] = *(const float4*)(Wp + (size_t)(i * 32) * K + ko);
            }
        }

#pragma unroll
        for (int kc = 0; kc < 32; kc += 8) {
            uint32_t af[2][4];
#pragma unroll
            for (int mi = 0; mi < 2; mi++) {
                int mr = wm * 32 + mi * 16 + gid;
                af[mi][0] = As[mr * TG_LDS + kc + tig];
                af[mi][1] = As[(mr + 8) * TG_LDS + kc + tig];
                af[mi][2] = As[mr * TG_LDS + kc + tig + 4];
                af[mi][3] = As[(mr + 8) * TG_LDS + kc + tig + 4];
            }
#pragma unroll
            for (int ni = 0; ni < 8; ni++) {
                int nr = wn * 64 + ni * 8 + gid;
                uint32_t b0 = Bs[nr * TG_LDS + kc + tig];
                uint32_t b1 = Bs[nr * TG_LDS + kc + tig + 4];
                mma_tf32(acc[0][ni], af[0], b0, b1);
                mma_tf32(acc[1][ni], af[1], b0, b1);
            }
        }
        __syncthreads();
    }

    // Epilogue with bias
#pragma unroll
    for (int ni = 0; ni < 8; ni++) {
        int col = n0 + wn * 64 + ni * 8 + tig * 2;
        float bv0 = bias[col];
        float bv1 = bias[col + 1];
#pragma unroll
        for (int mi = 0; mi < 2; mi++) {
            int r = m0 + wm * 32 + mi * 16 + gid;
            float2 o0 = make_float2(acc[mi][ni][0] + bv0, acc[mi][ni][1] + bv1);
            float2 o1 = make_float2(acc[mi][ni][2] + bv0, acc[mi][ni][3] + bv1);
            *(float2*)(Cmat + (size_t)r * N + col)       = o0;
            *(float2*)(Cmat + (size_t)(r + 8) * N + col) = o1;
        }
    }
}

// ---------------------------------------------------------------------------
// Fused attention: one CTA per (b,h). K (padded)/V in smem, q in registers
// (shfl broadcast), warp softmax, AV with smem-broadcast p.
// smem = 196*65 + 196*64 + 8*196 floats = 107,408 B  -> 2 CTAs/SM.
// ---------------------------------------------------------------------------
#define SK_LD 65
#define ATTN_SMEM_FLOATS (N_*SK_LD + N_*HD_ + 8*N_)

__global__ void __launch_bounds__(256)
attn_kernel(const float* __restrict__ qkv, float* __restrict__ out) {
    extern __shared__ float sm[];
    float* sk = sm;                       // [196][65]  k (padded rows)
    float* sv = sk + N_ * SK_LD;          // [196][64]  v
    float* sp = sv + N_ * HD_;            // [8][196]   per-warp p row

    const int tid = threadIdx.x;
    const int b   = blockIdx.x / H_;
    const int h   = blockIdx.x - b * H_;
    const float scale = 0.125f;           // 64^-0.5

    const float* base = qkv + (size_t)b * N_ * C3_ + h * HD_;
    for (int idx = tid; idx < N_ * HD_; idx += 256) {
        int n = idx >> 6, d = idx & 63;
        const float* src = base + (size_t)n * C3_ + d;
        sk[n * SK_LD + d] = src[C_];
        sv[idx]           = src[2 * C_];
    }
    __syncthreads();

    const int wid  = tid >> 5;
    const int lane = tid & 31;
    const float* rpbh = g_rpb + (size_t)h * (N_ * N_);

    for (int i = wid; i < N_; i += 8) {
        // q row in registers (warp-private)
        const float* qrow = base + (size_t)i * C3_;
        float q0 = qrow[lane] * scale;
        float q1 = qrow[lane + 32] * scale;

        float s[7];
#pragma unroll
        for (int t = 0; t < 7; t++) s[t] = 0.0f;

        const float* kbase = sk + lane * SK_LD;   // row lane, +t*32 rows
#pragma unroll 8
        for (int d = 0; d < 32; d++) {
            float qd = __shfl_sync(0xffffffffu, q0, d);
            const float* kr = kbase + d;
#pragma unroll
            for (int t = 0; t < 6; t++) s[t] += qd * kr[t * 32 * SK_LD];
            if (lane < 4) s[6] += qd * kr[6 * 32 * SK_LD];
        }
#pragma unroll 8
        for (int d = 0; d < 32; d++) {
            float qd = __shfl_sync(0xffffffffu, q1, d);
            const float* kr = kbase + d + 32;
#pragma unroll
            for (int t = 0; t < 6; t++) s[t] += qd * kr[t * 32 * SK_LD];
            if (lane < 4) s[6] += qd * kr[6 * 32 * SK_LD];
        }

        const float* rrow = rpbh + i * N_;
#pragma unroll
        for (int t = 0; t < 6; t++) s[t] += rrow[lane + t * 32];
        if (lane < 4) s[6] += rrow[lane + 192];
        else          s[6] = -3.4e38f;

        float mx = s[0];
#pragma unroll
        for (int t = 1; t < 7; t++) mx = fmaxf(mx, s[t]);
#pragma unroll
        for (int o = 16; o > 0; o >>= 1)
            mx = fmaxf(mx, __shfl_xor_sync(0xffffffffu, mx, o));

        float sum = 0.0f;
#pragma unroll
        for (int t = 0; t < 7; t++) {
            float e = (t < 6 || lane < 4) ? __expf(s[t] - mx) : 0.0f;
            s[t] = e;
            sum += e;
        }
#pragma unroll
        for (int o = 16; o > 0; o >>= 1)
            sum += __shfl_xor_sync(0xffffffffu, sum, o);
        float inv = 1.0f / sum;

        float* prow = sp + wid * N_;
#pragma unroll
        for (int t = 0; t < 6; t++) prow[lane + t * 32] = s[t] * inv;
        if (lane < 4) prow[lane + 192] = s[6] * inv;
        __syncwarp();

        float a0 = 0.f, a1 = 0.f, a2 = 0.f, a3 = 0.f;
        for (int j = 0; j < N_; j += 2) {
            float p0 = prow[j];
            float p1 = prow[j + 1];
            const float* v0 = sv + j * HD_ + lane;
            a0 += p0 * v0[0];
            a1 += p0 * v0[32];
            a2 += p1 * v0[HD_];
            a3 += p1 * v0[HD_ + 32];
        }
        a0 += a2;
        a1 += a3;

        float* orow = out + ((size_t)b * N_ + i) * C_ + h * HD_;
        orow[lane]      = a0;
        orow[lane + 32] = a1;
        __syncwarp();   // protect sp reuse next iteration
    }
}

// ---------------------------------------------------------------------------
// Launch
// ---------------------------------------------------------------------------
extern "C" void kernel_launch(void* const* d_in, const int* in_sizes, int n_in,
                              void* d_out, int out_size) {
    const float* x         = (const float*)d_in[0];
    const float* qkv_w     = (const float*)d_in[1];
    const float* q_bias    = (const float*)d_in[2];
    const float* v_bias    = (const float*)d_in[3];
    const float* rpb_table = (const float*)d_in[4];
    const float* proj_w    = (const float*)d_in[5];
    const float* proj_b    = (const float*)d_in[6];
    const int*   rel_index = (const int*)d_in[7];
    float*       out       = (float*)d_out;

    // Host-side, non-stream calls: legal during graph capture, idempotent.
    static const size_t attn_smem = ATTN_SMEM_FLOATS * sizeof(float);
    cudaFuncSetAttribute(attn_kernel,
                         cudaFuncAttributeMaxDynamicSharedMemorySize,
                         (int)attn_smem);

    float *qkvbuf, *attbuf, *biasbuf;
    cudaGetSymbolAddress((void**)&qkvbuf, g_qkv);
    cudaGetSymbolAddress((void**)&attbuf, g_att);
    cudaGetSymbolAddress((void**)&biasbuf, g_bias);

    // 1. fused qkv bias
    bias_init_kernel<<<(C3_ + 255) / 256, 256>>>(q_bias, v_bias);

    // 2. pre-gather relative position bias [H,N,N]
    rpb_init_kernel<<<(H_ * N_ * N_ + 255) / 256, 256>>>(rpb_table, rel_index);

    // 3. QKV GEMM: [B*N, C] x [3C, C]^T -> [B*N, 3C]  (tf32 MMA)
    {
        dim3 grid(C3_ / 128, (B_ * N_) / 128);
        tgemm_bias_kernel<<<grid, 256>>>(x, qkv_w, biasbuf, qkvbuf,
                                         B_ * N_, C3_, C_);
    }

    // 4. fused attention per (b,h)
    attn_kernel<<<B_ * H_, 256, attn_smem>>>(qkvbuf, attbuf);

    // 5. Proj GEMM: [B*N, C] x [C, C]^T -> d_out  (tf32 MMA)
    {
        dim3 grid(C_ / 128, (B_ * N_) / 128);
        tgemm_bias_kernel<<<grid, 256>>>(attbuf, proj_w, proj_b, out,
                                         B_ * N_, C_, C_);
    }
}

// round 5
// speedup vs baseline: 3.3114x; 1.6830x over previous
#include <cuda_runtime.h>
#include <cstdint>

#define B_   256
#define N_   196
#define C_   768
#define H_   12
#define HD_  64
#define C3_  2304

// Scratch (device globals: allocation-free per harness rules)
__device__ float g_qkv[(size_t)B_ * N_ * C3_];   // [B,N,3C]
__device__ float g_att[(size_t)B_ * N_ * C_];    // [B,N,C] attention output
__device__ float g_rpb[(size_t)H_ * N_ * N_];    // [H,N,N] pre-gathered bias
__device__ float g_bias[C3_];                    // fused qkv bias

// ---------------------------------------------------------------------------
// Small init kernels
// ---------------------------------------------------------------------------
__global__ void bias_init_kernel(const float* __restrict__ qb,
                                 const float* __restrict__ vb) {
    int i = blockIdx.x * blockDim.x + threadIdx.x;
    if (i < C3_) {
        float v = 0.0f;
        if (i < C_)            v = qb[i];
        else if (i >= 2 * C_)  v = vb[i - 2 * C_];
        g_bias[i] = v;
    }
}

__global__ void rpb_init_kernel(const float* __restrict__ table,
                                const int* __restrict__ rel) {
    int i = blockIdx.x * blockDim.x + threadIdx.x;
    if (i < H_ * N_ * N_) {
        int h  = i / (N_ * N_);
        int ij = i - h * (N_ * N_);
        g_rpb[i] = table[rel[ij] * H_ + h];
    }
}

// ---------------------------------------------------------------------------
// tf32 helpers
// ---------------------------------------------------------------------------
__device__ __forceinline__ uint32_t f2tf32(float f) {
    uint32_t r;
    asm("cvt.rna.tf32.f32 %0, %1;" : "=r"(r) : "f"(f));
    return r;
}

__device__ __forceinline__ void mma_tf32(float* c, const uint32_t* a,
                                         uint32_t b0, uint32_t b1) {
    asm volatile(
        "mma.sync.aligned.m16n8k8.row.col.f32.tf32.tf32.f32 "
        "{%0,%1,%2,%3}, {%4,%5,%6,%7}, {%8,%9}, {%0,%1,%2,%3};"
        : "+f"(c[0]), "+f"(c[1]), "+f"(c[2]), "+f"(c[3])
        : "r"(a[0]), "r"(a[1]), "r"(a[2]), "r"(a[3]), "r"(b0), "r"(b1));
}

// ---------------------------------------------------------------------------
// Tensor-core GEMM: C[M,N] = A[M,K] @ W[N,K]^T + bias[N]   (tf32 MMA)
// 128x128 CTA tile, BK=32, 256 threads (8 warps, 4m x 2n), warp tile m32n64.
// ---------------------------------------------------------------------------
#define TG_LDS 36   // padded smem row stride (elements)

__global__ void __launch_bounds__(256)
tgemm_bias_kernel(const float* __restrict__ A, const float* __restrict__ W,
                  const float* __restrict__ bias, float* __restrict__ Cmat,
                  int M, int N, int K) {
    __shared__ uint32_t As[128 * TG_LDS];
    __shared__ uint32_t Bs[128 * TG_LDS];

    const int tid  = threadIdx.x;
    const int lane = tid & 31;
    const int wid  = tid >> 5;
    const int gid  = lane >> 2;
    const int tig  = lane & 3;
    const int wm   = wid & 3;
    const int wn   = wid >> 2;
    const int m0   = blockIdx.y << 7;
    const int n0   = blockIdx.x << 7;

    const int row_ = tid >> 3;
    const int kq   = (tid & 7) << 2;

    const float* Ap = A + (size_t)(m0 + row_) * K + kq;
    const float* Wp = W + (size_t)(n0 + row_) * K + kq;

    float acc[2][8][4];
#pragma unroll
    for (int mi = 0; mi < 2; mi++)
#pragma unroll
        for (int ni = 0; ni < 8; ni++)
#pragma unroll
            for (int j = 0; j < 4; j++) acc[mi][ni][j] = 0.0f;

    float4 ap[4], bp[4];
#pragma unroll
    for (int i = 0; i < 4; i++) {
        ap[i] = *(const float4*)(Ap + (size_t)(i * 32) * K);
        bp[i] = *(const float4*)(Wp + (size_t)(i * 32) * K);
    }

    const int nT = K >> 5;
    for (int t = 0; t < nT; t++) {
#pragma unroll
        for (int i = 0; i < 4; i++) {
            uint32_t* da = &As[(row_ + i * 32) * TG_LDS + kq];
            da[0] = f2tf32(ap[i].x); da[1] = f2tf32(ap[i].y);
            da[2] = f2tf32(ap[i].z); da[3] = f2tf32(ap[i].w);
            uint32_t* db = &Bs[(row_ + i * 32) * TG_LDS + kq];
            db[0] = f2tf32(bp[i].x); db[1] = f2tf32(bp[i].y);
            db[2] = f2tf32(bp[i].z); db[3] = f2tf32(bp[i].w);
        }
        __syncthreads();

        if (t + 1 < nT) {
            int ko = (t + 1) << 5;
#pragma unroll
            for (int i = 0; i < 4; i++) {
                ap[i] = *(const float4*)(Ap + (size_t)(i * 32) * K + ko);
                bp[i] = *(const float4*)(Wp + (size_t)(i * 32) * K + ko);
            }
        }

#pragma unroll
        for (int kc = 0; kc < 32; kc += 8) {
            uint32_t af[2][4];
#pragma unroll
            for (int mi = 0; mi < 2; mi++) {
                int mr = wm * 32 + mi * 16 + gid;
                af[mi][0] = As[mr * TG_LDS + kc + tig];
                af[mi][1] = As[(mr + 8) * TG_LDS + kc + tig];
                af[mi][2] = As[mr * TG_LDS + kc + tig + 4];
                af[mi][3] = As[(mr + 8) * TG_LDS + kc + tig + 4];
            }
#pragma unroll
            for (int ni = 0; ni < 8; ni++) {
                int nr = wn * 64 + ni * 8 + gid;
                uint32_t b0 = Bs[nr * TG_LDS + kc + tig];
                uint32_t b1 = Bs[nr * TG_LDS + kc + tig + 4];
                mma_tf32(acc[0][ni], af[0], b0, b1);
                mma_tf32(acc[1][ni], af[1], b0, b1);
            }
        }
        __syncthreads();
    }

#pragma unroll
    for (int ni = 0; ni < 8; ni++) {
        int col = n0 + wn * 64 + ni * 8 + tig * 2;
        float bv0 = bias[col];
        float bv1 = bias[col + 1];
#pragma unroll
        for (int mi = 0; mi < 2; mi++) {
            int r = m0 + wm * 32 + mi * 16 + gid;
            float2 o0 = make_float2(acc[mi][ni][0] + bv0, acc[mi][ni][1] + bv1);
            float2 o1 = make_float2(acc[mi][ni][2] + bv0, acc[mi][ni][3] + bv1);
            *(float2*)(Cmat + (size_t)r * N + col)       = o0;
            *(float2*)(Cmat + (size_t)(r + 8) * N + col) = o1;
        }
    }
}

// ---------------------------------------------------------------------------
// MMA attention: one CTA per (b,h), 8 warps. K (tf32) and V^T (tf32) staged
// in smem once; each warp owns 16-row m-tiles with the full S row block in
// registers; softmax in registers (quad shfl); P->A-fragment via quad shfl
// (no smem round-trip); AV via tf32 MMA against V^T.
// ---------------------------------------------------------------------------
#define MT_TILES 13           // ceil(196/16)
#define NKT      25           // ceil(196/8)  (keys padded to 200)
#define KST      68           // K smem row stride (words): conflict-free
#define VST      212          // V^T smem row stride (words): conflict-free
#define ATTN_SMEM_WORDS (200 * KST + 64 * VST)

__global__ void __launch_bounds__(256)
attn_mma_kernel(const float* __restrict__ qkv, float* __restrict__ out) {
    extern __shared__ uint32_t smw[];
    uint32_t* sk  = smw;              // [200][KST] tf32 K  (rows 196..199 = 0)
    uint32_t* svt = smw + 200 * KST;  // [64][VST]  tf32 V^T (cols 196..199 = 0)

    const int tid = threadIdx.x;
    const int b   = blockIdx.x / H_;
    const int h   = blockIdx.x - b * H_;
    const float* base = qkv + (size_t)b * N_ * C3_ + h * HD_;

    // Stage K and V^T (coalesced global reads)
    for (int idx = tid; idx < N_ * HD_; idx += 256) {
        int n = idx >> 6, d = idx & 63;
        const float* src = base + (size_t)n * C3_ + d;
        sk[n * KST + d]   = f2tf32(src[C_]);
        svt[d * VST + n]  = f2tf32(src[2 * C_]);
    }
    // Zero pads (keys 196..199)
    for (int idx = tid; idx < 4 * HD_; idx += 256) {
        int n = 196 + (idx >> 6), d = idx & 63;
        sk[n * KST + d]  = 0;
        svt[d * VST + n] = 0;
    }
    __syncthreads();

    const int lane = tid & 31;
    const int wid  = tid >> 5;
    const int gid  = lane >> 2;   // 0..7
    const int tig  = lane & 3;    // 0..3
    const float* rpbh = g_rpb + (size_t)h * (N_ * N_);
    const float scale = 0.125f;   // 64^-0.5

    for (int mt = wid; mt < MT_TILES; mt += 8) {
        const int i0 = mt * 16;
        const int r0 = i0 + gid;
        const int r1 = i0 + gid + 8;
        const int qr0 = r0 < N_ ? r0 : N_ - 1;   // clamp (rows never written)
        const int qr1 = r1 < N_ ? r1 : N_ - 1;
        const float* q0p = base + (size_t)qr0 * C3_;
        const float* q1p = base + (size_t)qr1 * C3_;

        // Q A-fragments for 8 k-chunks (scaled, tf32)
        uint32_t aq[8][4];
#pragma unroll
        for (int kc = 0; kc < 8; kc++) {
            int c0 = kc * 8 + tig;
            aq[kc][0] = f2tf32(q0p[c0] * scale);
            aq[kc][1] = f2tf32(q1p[c0] * scale);
            aq[kc][2] = f2tf32(q0p[c0 + 4] * scale);
            aq[kc][3] = f2tf32(q1p[c0 + 4] * scale);
        }

        // S = Q K^T  (register-resident: 25 n-tiles x 4 frags)
        float sacc[NKT][4];
#pragma unroll
        for (int nt = 0; nt < NKT; nt++) {
            sacc[nt][0] = 0.f; sacc[nt][1] = 0.f;
            sacc[nt][2] = 0.f; sacc[nt][3] = 0.f;
        }
#pragma unroll
        for (int kc = 0; kc < 8; kc++) {         // kc outer: independent accs
#pragma unroll
            for (int nt = 0; nt < NKT; nt++) {
                const uint32_t* kb = sk + (nt * 8 + gid) * KST + kc * 8 + tig;
                mma_tf32(sacc[nt], aq[kc], kb[0], kb[4]);
            }
        }

        // + rpb, mask padded key columns
        const float* rb0 = rpbh + (size_t)qr0 * N_;
        const float* rb1 = rpbh + (size_t)qr1 * N_;
#pragma unroll
        for (int nt = 0; nt < NKT; nt++) {
            int col = nt * 8 + 2 * tig;
            if (col < N_) {
                float2 v0 = *(const float2*)(rb0 + col);
                float2 v1 = *(const float2*)(rb1 + col);
                sacc[nt][0] += v0.x; sacc[nt][1] += v0.y;
                sacc[nt][2] += v1.x; sacc[nt][3] += v1.y;
            } else {
                sacc[nt][0] = -1e30f; sacc[nt][1] = -1e30f;
                sacc[nt][2] = -1e30f; sacc[nt][3] = -1e30f;
            }
        }

        // Row softmax (rows r0 -> frags 0,1 ; r1 -> frags 2,3), quad reduce
        float mx0 = -1e30f, mx1 = -1e30f;
#pragma unroll
        for (int nt = 0; nt < NKT; nt++) {
            mx0 = fmaxf(mx0, fmaxf(sacc[nt][0], sacc[nt][1]));
            mx1 = fmaxf(mx1, fmaxf(sacc[nt][2], sacc[nt][3]));
        }
        mx0 = fmaxf(mx0, __shfl_xor_sync(0xffffffffu, mx0, 1));
        mx0 = fmaxf(mx0, __shfl_xor_sync(0xffffffffu, mx0, 2));
        mx1 = fmaxf(mx1, __shfl_xor_sync(0xffffffffu, mx1, 1));
        mx1 = fmaxf(mx1, __shfl_xor_sync(0xffffffffu, mx1, 2));

        float s0 = 0.f, s1 = 0.f;
#pragma unroll
        for (int nt = 0; nt < NKT; nt++) {
            sacc[nt][0] = __expf(sacc[nt][0] - mx0);
            sacc[nt][1] = __expf(sacc[nt][1] - mx0);
            sacc[nt][2] = __expf(sacc[nt][2] - mx1);
            sacc[nt][3] = __expf(sacc[nt][3] - mx1);
            s0 += sacc[nt][0] + sacc[nt][1];
            s1 += sacc[nt][2] + sacc[nt][3];
        }
        s0 += __shfl_xor_sync(0xffffffffu, s0, 1);
        s0 += __shfl_xor_sync(0xffffffffu, s0, 2);
        s1 += __shfl_xor_sync(0xffffffffu, s1, 1);
        s1 += __shfl_xor_sync(0xffffffffu, s1, 2);
        const float inv0 = 1.0f / s0;
        const float inv1 = 1.0f / s1;

        // O = P V  (P converted C-frag -> A-frag via quad shfl)
        float oacc[8][4];
#pragma unroll
        for (int dt = 0; dt < 8; dt++) {
            oacc[dt][0] = 0.f; oacc[dt][1] = 0.f;
            oacc[dt][2] = 0.f; oacc[dt][3] = 0.f;
        }
        const int s_lo = tig >> 1;       // quad source sub-lane for col tig
        const int s_hi = s_lo + 2;       // for col tig+4
        const bool odd = (tig & 1);
#pragma unroll
        for (int kc = 0; kc < NKT; kc++) {
            float x0 = __shfl_sync(0xffffffffu, sacc[kc][0], s_lo, 4);
            float x1 = __shfl_sync(0xffffffffu, sacc[kc][1], s_lo, 4);
            float y0 = __shfl_sync(0xffffffffu, sacc[kc][2], s_lo, 4);
            float y1 = __shfl_sync(0xffffffffu, sacc[kc][3], s_lo, 4);
            float z0 = __shfl_sync(0xffffffffu, sacc[kc][0], s_hi, 4);
            float z1 = __shfl_sync(0xffffffffu, sacc[kc][1], s_hi, 4);
            float w0 = __shfl_sync(0xffffffffu, sacc[kc][2], s_hi, 4);
            float w1 = __shfl_sync(0xffffffffu, sacc[kc][3], s_hi, 4);
            uint32_t ap[4];
            ap[0] = f2tf32(odd ? x1 : x0);
            ap[1] = f2tf32(odd ? y1 : y0);
            ap[2] = f2tf32(odd ? z1 : z0);
            ap[3] = f2tf32(odd ? w1 : w0);
            const uint32_t* vb = svt + gid * VST + kc * 8 + tig;
#pragma unroll
            for (int dt = 0; dt < 8; dt++) {
                mma_tf32(oacc[dt], ap, vb[dt * 8 * VST], vb[dt * 8 * VST + 4]);
            }
        }

        // Epilogue: normalize + write (guard padded rows)
        const bool ok0 = r0 < N_;
        const bool ok1 = r1 < N_;
        float* o0 = out + ((size_t)b * N_ + r0) * C_ + h * HD_;
        float* o1 = out + ((size_t)b * N_ + r1) * C_ + h * HD_;
#pragma unroll
        for (int dt = 0; dt < 8; dt++) {
            int col = dt * 8 + 2 * tig;
            if (ok0)
                *(float2*)(o0 + col) = make_float2(oacc[dt][0] * inv0,
                                                   oacc[dt][1] * inv0);
            if (ok1)
                *(float2*)(o1 + col) = make_float2(oacc[dt][2] * inv1,
                                                   oacc[dt][3] * inv1);
        }
    }
}

// ---------------------------------------------------------------------------
// Launch
// ---------------------------------------------------------------------------
extern "C" void kernel_launch(void* const* d_in, const int* in_sizes, int n_in,
                              void* d_out, int out_size) {
    const float* x         = (const float*)d_in[0];
    const float* qkv_w     = (const float*)d_in[1];
    const float* q_bias    = (const float*)d_in[2];
    const float* v_bias    = (const float*)d_in[3];
    const float* rpb_table = (const float*)d_in[4];
    const float* proj_w    = (const float*)d_in[5];
    const float* proj_b    = (const float*)d_in[6];
    const int*   rel_index = (const int*)d_in[7];
    float*       out       = (float*)d_out;

    static const size_t attn_smem = (size_t)ATTN_SMEM_WORDS * 4;
    cudaFuncSetAttribute(attn_mma_kernel,
                         cudaFuncAttributeMaxDynamicSharedMemorySize,
                         (int)attn_smem);

    float *qkvbuf, *attbuf, *biasbuf;
    cudaGetSymbolAddress((void**)&qkvbuf, g_qkv);
    cudaGetSymbolAddress((void**)&attbuf, g_att);
    cudaGetSymbolAddress((void**)&biasbuf, g_bias);

    // 1. fused qkv bias
    bias_init_kernel<<<(C3_ + 255) / 256, 256>>>(q_bias, v_bias);

    // 2. pre-gather relative position bias [H,N,N]
    rpb_init_kernel<<<(H_ * N_ * N_ + 255) / 256, 256>>>(rpb_table, rel_index);

    // 3. QKV GEMM: [B*N, C] x [3C, C]^T -> [B*N, 3C]  (tf32 MMA)
    {
        dim3 grid(C3_ / 128, (B_ * N_) / 128);
        tgemm_bias_kernel<<<grid, 256>>>(x, qkv_w, biasbuf, qkvbuf,
                                         B_ * N_, C3_, C_);
    }

    // 4. fused MMA attention per (b,h)
    attn_mma_kernel<<<B_ * H_, 256, attn_smem>>>(qkvbuf, attbuf);

    // 5. Proj GEMM: [B*N, C] x [C, C]^T -> d_out  (tf32 MMA)
    {
        dim3 grid(C_ / 128, (B_ * N_) / 128);
        tgemm_bias_kernel<<<grid, 256>>>(attbuf, proj_w, proj_b, out,
                                         B_ * N_, C_, C_);
    }
}

// round 7
// speedup vs baseline: 3.7060x; 1.1192x over previous
#include <cuda_runtime.h>
#include <cstdint>

#define B_   256
#define N_   196
#define C_   768
#define H_   12
#define HD_  64
#define C3_  2304

// Scratch (device globals: allocation-free per harness rules)
__device__ float    g_qkv[(size_t)B_ * N_ * C3_];   // [B,N,3C] fp32 qkv
__device__ uint32_t g_att[(size_t)B_ * N_ * C_];    // [B,N,C] attn out (tf32 bits)
__device__ float    g_rpb[(size_t)H_ * N_ * N_];    // [H,N,N] pre-gathered bias
__device__ float    g_bias[C3_];                    // fused qkv bias
__device__ uint32_t g_xt[(size_t)B_ * N_ * C_];     // x in tf32 bits
__device__ uint32_t g_wt[C3_ * C_];                 // qkv_w in tf32 bits
__device__ uint32_t g_pwt[C_ * C_];                 // proj_w in tf32 bits

// ---------------------------------------------------------------------------
// tf32 helpers
// ---------------------------------------------------------------------------
__device__ __forceinline__ uint32_t f2tf32(float f) {
    uint32_t r;
    asm("cvt.rna.tf32.f32 %0, %1;" : "=r"(r) : "f"(f));
    return r;
}

__device__ __forceinline__ void mma_tf32(float* c, const uint32_t* a,
                                         uint32_t b0, uint32_t b1) {
    asm volatile(
        "mma.sync.aligned.m16n8k8.row.col.f32.tf32.tf32.f32 "
        "{%0,%1,%2,%3}, {%4,%5,%6,%7}, {%8,%9}, {%0,%1,%2,%3};"
        : "+f"(c[0]), "+f"(c[1]), "+f"(c[2]), "+f"(c[3])
        : "r"(a[0]), "r"(a[1]), "r"(a[2]), "r"(a[3]), "r"(b0), "r"(b1));
}

#define CP16(dst_u32, src_ptr) \
    asm volatile("cp.async.ca.shared.global [%0], [%1], 16;" \
                 :: "r"(dst_u32), "l"(src_ptr))

__device__ __forceinline__ uint32_t smem_u32(const void* p) {
    return (uint32_t)__cvta_generic_to_shared(p);
}

// ---------------------------------------------------------------------------
// Small init kernels
// ---------------------------------------------------------------------------
__global__ void bias_init_kernel(const float* __restrict__ qb,
                                 const float* __restrict__ vb) {
    int i = blockIdx.x * blockDim.x + threadIdx.x;
    if (i < C3_) {
        float v = 0.0f;
        if (i < C_)            v = qb[i];
        else if (i >= 2 * C_)  v = vb[i - 2 * C_];
        g_bias[i] = v;
    }
}

__global__ void rpb_init_kernel(const float* __restrict__ table,
                                const int* __restrict__ rel) {
    int i = blockIdx.x * blockDim.x + threadIdx.x;
    if (i < H_ * N_ * N_) {
        int h  = i / (N_ * N_);
        int ij = i - h * (N_ * N_);
        g_rpb[i] = table[rel[ij] * H_ + h];
    }
}

// fp32 -> tf32 bits, vectorized
__global__ void cvt_tf32_kernel(const float4* __restrict__ src,
                                uint4* __restrict__ dst, int n4) {
    int i = blockIdx.x * blockDim.x + threadIdx.x;
    if (i < n4) {
        float4 v = src[i];
        dst[i] = make_uint4(f2tf32(v.x), f2tf32(v.y), f2tf32(v.z), f2tf32(v.w));
    }
}

// ---------------------------------------------------------------------------
// Tensor-core GEMM v2: C[M,N] = A[M,K] @ W[N,K]^T + bias[N]
// A, W pre-converted to tf32 bits. 128x128 CTA tile, BK=32, 256 threads,
// cp.async double-buffered smem, 8 warps (4m x 2n), warp tile m32n64.
// ---------------------------------------------------------------------------
#define TG_LDS  36                 // padded smem row stride (words)
#define TG_TILE (128 * TG_LDS)     // words per matrix per stage
#define TG_SMEM (4 * TG_TILE * 4)  // bytes: 2 stages x 2 matrices

__global__ void __launch_bounds__(256)
tgemm_bias_kernel(const uint32_t* __restrict__ A, const uint32_t* __restrict__ W,
                  const float* __restrict__ bias, float* __restrict__ Cmat,
                  int M, int N, int K) {
    extern __shared__ uint32_t dynsm[];
    uint32_t* As0 = dynsm;
    uint32_t* As1 = dynsm + TG_TILE;
    uint32_t* Bs0 = dynsm + 2 * TG_TILE;
    uint32_t* Bs1 = dynsm + 3 * TG_TILE;

    const int tid  = threadIdx.x;
    const int lane = tid & 31;
    const int wid  = tid >> 5;
    const int gid  = lane >> 2;
    const int tig  = lane & 3;
    const int wm   = wid & 3;
    const int wn   = wid >> 2;
    const int m0   = blockIdx.y << 7;
    const int n0   = blockIdx.x << 7;

    // cp.async assignment: 4 x 16B per matrix per thread (128x32 words)
    const int row_ = tid >> 3;
    const int kq   = (tid & 7) << 2;

    const uint32_t* Ap = A + (size_t)(m0 + row_) * K + kq;
    const uint32_t* Wp = W + (size_t)(n0 + row_) * K + kq;

    const uint32_t offs = (uint32_t)(row_ * TG_LDS + kq) * 4;
    const uint32_t aAddr0 = smem_u32(As0) + offs;
    const uint32_t aAddr1 = smem_u32(As1) + offs;
    const uint32_t bAddr0 = smem_u32(Bs0) + offs;
    const uint32_t bAddr1 = smem_u32(Bs1) + offs;
    const uint32_t rowStep = 32 * TG_LDS * 4;   // bytes per 32-row hop

    float acc[2][8][4];
#pragma unroll
    for (int mi = 0; mi < 2; mi++)
#pragma unroll
        for (int ni = 0; ni < 8; ni++)
#pragma unroll
            for (int j = 0; j < 4; j++) acc[mi][ni][j] = 0.0f;

    const int nT = K >> 5;

    // Issue tile 0
    {
#pragma unroll
        for (int i = 0; i < 4; i++) {
            CP16(aAddr0 + i * rowStep, Ap + (size_t)(i * 32) * K);
            CP16(bAddr0 + i * rowStep, Wp + (size_t)(i * 32) * K);
        }
        asm volatile("cp.async.commit_group;");
    }

    for (int t = 0; t < nT; t++) {
        if (t + 1 < nT) {
            const int s = (t + 1) & 1;
            const uint32_t aA = s ? aAddr1 : aAddr0;
            const uint32_t bA = s ? bAddr1 : bAddr0;
            const size_t ko = (size_t)(t + 1) << 5;
#pragma unroll
            for (int i = 0; i < 4; i++) {
                CP16(aA + i * rowStep, Ap + (size_t)(i * 32) * K + ko);
                CP16(bA + i * rowStep, Wp + (size_t)(i * 32) * K + ko);
            }
            asm volatile("cp.async.commit_group;");
            asm volatile("cp.async.wait_group 1;");
        } else {
            asm volatile("cp.async.wait_group 0;");
        }
        __syncthreads();

        const uint32_t* pA = (t & 1) ? As1 : As0;
        const uint32_t* pB = (t & 1) ? Bs1 : Bs0;

#pragma unroll
        for (int kc = 0; kc < 32; kc += 8) {
            uint32_t af[2][4];
#pragma unroll
            for (int mi = 0; mi < 2; mi++) {
                int mr = wm * 32 + mi * 16 + gid;
                af[mi][0] = pA[mr * TG_LDS + kc + tig];
                af[mi][1] = pA[(mr + 8) * TG_LDS + kc + tig];
                af[mi][2] = pA[mr * TG_LDS + kc + tig + 4];
                af[mi][3] = pA[(mr + 8) * TG_LDS + kc + tig + 4];
            }
#pragma unroll
            for (int ni = 0; ni < 8; ni++) {
                int nr = wn * 64 + ni * 8 + gid;
                uint32_t b0 = pB[nr * TG_LDS + kc + tig];
                uint32_t b1 = pB[nr * TG_LDS + kc + tig + 4];
                mma_tf32(acc[0][ni], af[0], b0, b1);
                mma_tf32(acc[1][ni], af[1], b0, b1);
            }
        }
        __syncthreads();   // protect buffer (t&1) before it is re-filled
    }

    // Epilogue with bias (fp32 out)
#pragma unroll
    for (int ni = 0; ni < 8; ni++) {
        int col = n0 + wn * 64 + ni * 8 + tig * 2;
        float bv0 = bias[col];
        float bv1 = bias[col + 1];
#pragma unroll
        for (int mi = 0; mi < 2; mi++) {
            int r = m0 + wm * 32 + mi * 16 + gid;
            float2 o0 = make_float2(acc[mi][ni][0] + bv0, acc[mi][ni][1] + bv1);
            float2 o1 = make_float2(acc[mi][ni][2] + bv0, acc[mi][ni][3] + bv1);
            *(float2*)(Cmat + (size_t)r * N + col)       = o0;
            *(float2*)(Cmat + (size_t)(r + 8) * N + col) = o1;
        }
    }
}

// ---------------------------------------------------------------------------
// MMA attention: one CTA per (b,h), 8 warps. K (tf32) and V^T (tf32) staged
// in smem once; per-warp 16-row m-tiles, register-resident S, softmax in
// registers, P->A-frag via quad shfl, AV via tf32 MMA. Output = tf32 bits
// (feeds proj GEMM directly).
// ---------------------------------------------------------------------------
#define MT_TILES 13           // ceil(196/16)
#define NKT      25           // ceil(196/8)  (keys padded to 200)
#define KST      68           // K smem row stride (words): conflict-free
#define VST      212          // V^T smem row stride (words): conflict-free
#define ATTN_SMEM_WORDS (200 * KST + 64 * VST)

__global__ void __launch_bounds__(256)
attn_mma_kernel(const float* __restrict__ qkv, uint32_t* __restrict__ out) {
    extern __shared__ uint32_t smw[];
    uint32_t* sk  = smw;              // [200][KST] tf32 K  (rows 196..199 = 0)
    uint32_t* svt = smw + 200 * KST;  // [64][VST]  tf32 V^T (cols 196..199 = 0)

    const int tid = threadIdx.x;
    const int b   = blockIdx.x / H_;
    const int h   = blockIdx.x - b * H_;
    const float* base = qkv + (size_t)b * N_ * C3_ + h * HD_;

    for (int idx = tid; idx < N_ * HD_; idx += 256) {
        int n = idx >> 6, d = idx & 63;
        const float* src = base + (size_t)n * C3_ + d;
        sk[n * KST + d]  = f2tf32(src[C_]);
        svt[d * VST + n] = f2tf32(src[2 * C_]);
    }
    for (int idx = tid; idx < 4 * HD_; idx += 256) {
        int n = 196 + (idx >> 6), d = idx & 63;
        sk[n * KST + d]  = 0;
        svt[d * VST + n] = 0;
    }
    __syncthreads();

    const int lane = tid & 31;
    const int wid  = tid >> 5;
    const int gid  = lane >> 2;
    const int tig  = lane & 3;
    const float* rpbh = g_rpb + (size_t)h * (N_ * N_);
    const float scale = 0.125f;

    for (int mt = wid; mt < MT_TILES; mt += 8) {
        const int i0 = mt * 16;
        const int r0 = i0 + gid;
        const int r1 = i0 + gid + 8;
        const int qr0 = r0 < N_ ? r0 : N_ - 1;
        const int qr1 = r1 < N_ ? r1 : N_ - 1;
        const float* q0p = base + (size_t)qr0 * C3_;
        const float* q1p = base + (size_t)qr1 * C3_;

        uint32_t aq[8][4];
#pragma unroll
        for (int kc = 0; kc < 8; kc++) {
            int c0 = kc * 8 + tig;
            aq[kc][0] = f2tf32(q0p[c0] * scale);
            aq[kc][1] = f2tf32(q1p[c0] * scale);
            aq[kc][2] = f2tf32(q0p[c0 + 4] * scale);
            aq[kc][3] = f2tf32(q1p[c0 + 4] * scale);
        }

        float sacc[NKT][4];
#pragma unroll
        for (int nt = 0; nt < NKT; nt++) {
            sacc[nt][0] = 0.f; sacc[nt][1] = 0.f;
            sacc[nt][2] = 0.f; sacc[nt][3] = 0.f;
        }
#pragma unroll
        for (int kc = 0; kc < 8; kc++) {
#pragma unroll
            for (int nt = 0; nt < NKT; nt++) {
                const uint32_t* kb = sk + (nt * 8 + gid) * KST + kc * 8 + tig;
                mma_tf32(sacc[nt], aq[kc], kb[0], kb[4]);
            }
        }

        const float* rb0 = rpbh + (size_t)qr0 * N_;
        const float* rb1 = rpbh + (size_t)qr1 * N_;
#pragma unroll
        for (int nt = 0; nt < NKT; nt++) {
            int col = nt * 8 + 2 * tig;
            if (col < N_) {
                float2 v0 = *(const float2*)(rb0 + col);
                float2 v1 = *(const float2*)(rb1 + col);
                sacc[nt][0] += v0.x; sacc[nt][1] += v0.y;
                sacc[nt][2] += v1.x; sacc[nt][3] += v1.y;
            } else {
                sacc[nt][0] = -1e30f; sacc[nt][1] = -1e30f;
                sacc[nt][2] = -1e30f; sacc[nt][3] = -1e30f;
            }
        }

        float mx0 = -1e30f, mx1 = -1e30f;
#pragma unroll
        for (int nt = 0; nt < NKT; nt++) {
            mx0 = fmaxf(mx0, fmaxf(sacc[nt][0], sacc[nt][1]));
            mx1 = fmaxf(mx1, fmaxf(sacc[nt][2], sacc[nt][3]));
        }
        mx0 = fmaxf(mx0, __shfl_xor_sync(0xffffffffu, mx0, 1));
        mx0 = fmaxf(mx0, __shfl_xor_sync(0xffffffffu, mx0, 2));
        mx1 = fmaxf(mx1, __shfl_xor_sync(0xffffffffu, mx1, 1));
        mx1 = fmaxf(mx1, __shfl_xor_sync(0xffffffffu, mx1, 2));

        float s0 = 0.f, s1 = 0.f;
#pragma unroll
        for (int nt = 0; nt < NKT; nt++) {
            sacc[nt][0] = __expf(sacc[nt][0] - mx0);
            sacc[nt][1] = __expf(sacc[nt][1] - mx0);
            sacc[nt][2] = __expf(sacc[nt][2] - mx1);
            sacc[nt][3] = __expf(sacc[nt][3] - mx1);
            s0 += sacc[nt][0] + sacc[nt][1];
            s1 += sacc[nt][2] + sacc[nt][3];
        }
        s0 += __shfl_xor_sync(0xffffffffu, s0, 1);
        s0 += __shfl_xor_sync(0xffffffffu, s0, 2);
        s1 += __shfl_xor_sync(0xffffffffu, s1, 1);
        s1 += __shfl_xor_sync(0xffffffffu, s1, 2);
        const float inv0 = 1.0f / s0;
        const float inv1 = 1.0f / s1;

        float oacc[8][4];
#pragma unroll
        for (int dt = 0; dt < 8; dt++) {
            oacc[dt][0] = 0.f; oacc[dt][1] = 0.f;
            oacc[dt][2] = 0.f; oacc[dt][3] = 0.f;
        }
        const int s_lo = tig >> 1;
        const int s_hi = s_lo + 2;
        const bool odd = (tig & 1);
#pragma unroll
        for (int kc = 0; kc < NKT; kc++) {
            float x0 = __shfl_sync(0xffffffffu, sacc[kc][0], s_lo, 4);
            float x1 = __shfl_sync(0xffffffffu, sacc[kc][1], s_lo, 4);
            float y0 = __shfl_sync(0xffffffffu, sacc[kc][2], s_lo, 4);
            float y1 = __shfl_sync(0xffffffffu, sacc[kc][3], s_lo, 4);
            float z0 = __shfl_sync(0xffffffffu, sacc[kc][0], s_hi, 4);
            float z1 = __shfl_sync(0xffffffffu, sacc[kc][1], s_hi, 4);
            float w0 = __shfl_sync(0xffffffffu, sacc[kc][2], s_hi, 4);
            float w1 = __shfl_sync(0xffffffffu, sacc[kc][3], s_hi, 4);
            uint32_t ap[4];
            ap[0] = f2tf32(odd ? x1 : x0);
            ap[1] = f2tf32(odd ? y1 : y0);
            ap[2] = f2tf32(odd ? z1 : z0);
            ap[3] = f2tf32(odd ? w1 : w0);
            const uint32_t* vb = svt + gid * VST + kc * 8 + tig;
#pragma unroll
            for (int dt = 0; dt < 8; dt++) {
                mma_tf32(oacc[dt], ap, vb[dt * 8 * VST], vb[dt * 8 * VST + 4]);
            }
        }

        const bool ok0 = r0 < N_;
        const bool ok1 = r1 < N_;
        uint32_t* o0 = out + ((size_t)b * N_ + r0) * C_ + h * HD_;
        uint32_t* o1 = out + ((size_t)b * N_ + r1) * C_ + h * HD_;
#pragma unroll
        for (int dt = 0; dt < 8; dt++) {
            int col = dt * 8 + 2 * tig;
            if (ok0)
                *(uint2*)(o0 + col) = make_uint2(f2tf32(oacc[dt][0] * inv0),
                                                 f2tf32(oacc[dt][1] * inv0));
            if (ok1)
                *(uint2*)(o1 + col) = make_uint2(f2tf32(oacc[dt][2] * inv1),
                                                 f2tf32(oacc[dt][3] * inv1));
        }
    }
}

// ---------------------------------------------------------------------------
// Launch
// ---------------------------------------------------------------------------
extern "C" void kernel_launch(void* const* d_in, const int* in_sizes, int n_in,
                              void* d_out, int out_size) {
    const float* x         = (const float*)d_in[0];
    const float* qkv_w     = (const float*)d_in[1];
    const float* q_bias    = (const float*)d_in[2];
    const float* v_bias    = (const float*)d_in[3];
    const float* rpb_table = (const float*)d_in[4];
    const float* proj_w    = (const float*)d_in[5];
    const float* proj_b    = (const float*)d_in[6];
    const int*   rel_index = (const int*)d_in[7];
    float*       out       = (float*)d_out;

    static const size_t attn_smem = (size_t)ATTN_SMEM_WORDS * 4;
    cudaFuncSetAttribute(attn_mma_kernel,
                         cudaFuncAttributeMaxDynamicSharedMemorySize,
                         (int)attn_smem);
    cudaFuncSetAttribute(tgemm_bias_kernel,
                         cudaFuncAttributeMaxDynamicSharedMemorySize,
                         (int)TG_SMEM);

    float *qkvbuf, *biasbuf;
    uint32_t *attbuf, *xtbuf, *wtbuf, *pwtbuf;
    cudaGetSymbolAddress((void**)&qkvbuf, g_qkv);
    cudaGetSymbolAddress((void**)&attbuf, g_att);
    cudaGetSymbolAddress((void**)&biasbuf, g_bias);
    cudaGetSymbolAddress((void**)&xtbuf, g_xt);
    cudaGetSymbolAddress((void**)&wtbuf, g_wt);
    cudaGetSymbolAddress((void**)&pwtbuf, g_pwt);

    // 1. fused qkv bias + rpb gather
    bias_init_kernel<<<(C3_ + 255) / 256, 256>>>(q_bias, v_bias);
    rpb_init_kernel<<<(H_ * N_ * N_ + 255) / 256, 256>>>(rpb_table, rel_index);

    // 2. pre-convert GEMM operands to tf32
    {
        int n4x = (B_ * N_ * C_) / 4;
        cvt_tf32_kernel<<<(n4x + 255) / 256, 256>>>((const float4*)x,
                                                    (uint4*)xtbuf, n4x);
        int n4w = (C3_ * C_) / 4;
        cvt_tf32_kernel<<<(n4w + 255) / 256, 256>>>((const float4*)qkv_w,
                                                    (uint4*)wtbuf, n4w);
        int n4p = (C_ * C_) / 4;
        cvt_tf32_kernel<<<(n4p + 255) / 256, 256>>>((const float4*)proj_w,
                                                    (uint4*)pwtbuf, n4p);
    }

    // 3. QKV GEMM: [B*N, C] x [3C, C]^T -> [B*N, 3C]  (tf32 MMA, cp.async)
    {
        dim3 grid(C3_ / 128, (B_ * N_) / 128);
        tgemm_bias_kernel<<<grid, 256, TG_SMEM>>>(xtbuf, wtbuf, biasbuf,
                                                  qkvbuf, B_ * N_, C3_, C_);
    }

    // 4. fused MMA attention per (b,h) -> tf32-bit output
    attn_mma_kernel<<<B_ * H_, 256, attn_smem>>>(qkvbuf, attbuf);

    // 5. Proj GEMM: [B*N, C] x [C, C]^T -> d_out  (tf32 MMA, cp.async)
    {
        dim3 grid(C_ / 128, (B_ * N_) / 128);
        tgemm_bias_kernel<<<grid, 256, TG_SMEM>>>(attbuf, pwtbuf, proj_b,
                                                  out, B_ * N_, C_, C_);
    }
}